// round 9
// baseline (speedup 1.0000x reference)
#include <cuda_runtime.h>
#include <cstdint>

#define NN   4096
#define FIN  256
#define FOUT 64
#define HD   64
#define MAXD 64
#define NG   256   // 4*HD

typedef unsigned long long u64;

// ---------------- scratch ----------------
__device__ float g_Wh [NN*FOUT];
__device__ float g_Wh2[NN*FOUT];
__device__ float g_s1 [NN];
__device__ float g_s2 [NN];
__device__ int   g_src[NN*MAXD];
__device__ float g_Gx [NN*NG];       // [j][(g&31)*8 + (g>>5)]  (lane*8 + q)
__device__ int   g_binCount[MAXD];
__device__ int   g_binCur  [MAXD];
__device__ int   g_perm[NN];         // rows sorted by seq_length DESCENDING

__global__ void k_init() { if (threadIdx.x < MAXD) g_binCount[threadIdx.x] = 0; }

// ---------------- f32x2 helpers ----------------
__device__ __forceinline__ void fma2(u64& d, u64 a, u64 b) {
    asm("fma.rn.f32x2 %0, %1, %2, %0;" : "+l"(d) : "l"(a), "l"(b));
}
__device__ __forceinline__ u64 add2(u64 a, u64 b) {
    u64 r;
    asm("add.rn.f32x2 %0, %1, %2;" : "=l"(r) : "l"(a), "l"(b));
    return r;
}
__device__ __forceinline__ u64 pack2(float x, float y) {
    u64 r;
    asm("mov.b64 %0, {%1, %2};" : "=l"(r) : "r"(__float_as_uint(x)), "r"(__float_as_uint(y)));
    return r;
}
__device__ __forceinline__ float2 unpack2(u64 v) {
    unsigned lo, hi;
    asm("mov.b64 {%0, %1}, %2;" : "=r"(lo), "=r"(hi) : "l"(v));
    float2 f; f.x = __uint_as_float(lo); f.y = __uint_as_float(hi);
    return f;
}
__device__ __forceinline__ void barpair(int id) {
    asm volatile("bar.sync %0, %1;" :: "r"(id), "r"(64) : "memory");
}

// ---------------- Wh = h @ W ----------------
__global__ void k_wh(const float* __restrict__ h, const float* __restrict__ W) {
    __shared__ float sh[16*FIN];
    int row0 = blockIdx.x * 16;
    for (int idx = threadIdx.x; idx < 16*FIN; idx += 256)
        sh[idx] = h[row0*FIN + idx];
    __syncthreads();
    int f   = threadIdx.x & 63;
    int grp = threadIdx.x >> 6;
    const float* hr = sh + grp*4*FIN;
    float a0=0.f, a1=0.f, a2=0.f, a3=0.f;
    for (int k = 0; k < FIN; k++) {
        float w = W[k*FOUT + f];
        a0 += hr[k]*w; a1 += hr[FIN+k]*w; a2 += hr[2*FIN+k]*w; a3 += hr[3*FIN+k]*w;
    }
    int r0 = row0 + grp*4;
    g_Wh[(r0+0)*FOUT+f]=a0; g_Wh[(r0+1)*FOUT+f]=a1;
    g_Wh[(r0+2)*FOUT+f]=a2; g_Wh[(r0+3)*FOUT+f]=a3;
}

// ---------------- s1 = Wh@a1, s2 = Wh@a2 ----------------
__global__ void k_s12(const float* __restrict__ a) {
    int w    = (blockIdx.x*blockDim.x + threadIdx.x) >> 5;
    int lane = threadIdx.x & 31;
    float w0 = g_Wh[w*FOUT + lane], w1 = g_Wh[w*FOUT + lane + 32];
    float v1 = w0*a[lane]      + w1*a[lane+32];
    float v2 = w0*a[FOUT+lane] + w1*a[FOUT+lane+32];
    #pragma unroll
    for (int o = 16; o; o >>= 1) {
        v1 += __shfl_down_sync(0xffffffffu, v1, o);
        v2 += __shfl_down_sync(0xffffffffu, v2, o);
    }
    if (lane == 0) { g_s1[w] = v1; g_s2[w] = v2; }
}

// ---------------- attention ----------------
__global__ void k_att(const float* __restrict__ adj, const int* __restrict__ seqlen) {
    __shared__ int   s_wsum[8];
    __shared__ int   s_woff[8];
    __shared__ int   s_total;
    __shared__ int   s_nbr[MAXD];
    __shared__ float s_att[MAXD];
    __shared__ float s_red[4];
    int i    = blockIdx.x;
    int tid  = threadIdx.x;
    int lane = tid & 31;
    int wid  = tid >> 5;
    const float4* arow4 = reinterpret_cast<const float4*>(adj + (size_t)i * NN);

    float4 v0 = arow4[tid];
    float4 v1 = arow4[tid + 256];
    float4 v2 = arow4[tid + 512];
    float4 v3 = arow4[tid + 768];
    int loc[16]; int c = 0;
    {
        int j0 = 4*tid;
        if (v0.x>0.f) loc[c++]=j0;   if (v0.y>0.f) loc[c++]=j0+1;
        if (v0.z>0.f) loc[c++]=j0+2; if (v0.w>0.f) loc[c++]=j0+3;
        int j1 = 4*(tid+256);
        if (v1.x>0.f) loc[c++]=j1;   if (v1.y>0.f) loc[c++]=j1+1;
        if (v1.z>0.f) loc[c++]=j1+2; if (v1.w>0.f) loc[c++]=j1+3;
        int j2 = 4*(tid+512);
        if (v2.x>0.f) loc[c++]=j2;   if (v2.y>0.f) loc[c++]=j2+1;
        if (v2.z>0.f) loc[c++]=j2+2; if (v2.w>0.f) loc[c++]=j2+3;
        int j3 = 4*(tid+768);
        if (v3.x>0.f) loc[c++]=j3;   if (v3.y>0.f) loc[c++]=j3+1;
        if (v3.z>0.f) loc[c++]=j3+2; if (v3.w>0.f) loc[c++]=j3+3;
    }
    int inc = c;
    #pragma unroll
    for (int o = 1; o < 32; o <<= 1) {
        int n = __shfl_up_sync(0xffffffffu, inc, o);
        if (lane >= o) inc += n;
    }
    if (lane == 31) s_wsum[wid] = inc;
    __syncthreads();
    if (tid < 8) {
        int v = s_wsum[tid];
        #pragma unroll
        for (int o = 1; o < 8; o <<= 1) {
            int n = __shfl_up_sync(0xffu, v, o);
            if (tid >= o) v += n;
        }
        s_woff[tid] = v - s_wsum[tid];
        if (tid == 7) s_total = v;
    }
    __syncthreads();
    int base = s_woff[wid] + inc - c;
    for (int j = 0; j < c; j++) s_nbr[base + j] = loc[j];
    int K = s_total;
    __syncthreads();

    float e = 0.f; int jj = -1;
    if (tid < K) {
        jj = s_nbr[tid];
        float v = g_s1[i] + g_s2[jj];
        e = v > 0.f ? v : 0.2f * v;
    }
    if (tid < 64) {
        float m = (tid < K) ? e : -3.0e38f;
        #pragma unroll
        for (int o = 16; o; o >>= 1) m = fmaxf(m, __shfl_xor_sync(0xffffffffu, m, o));
        if ((tid & 31) == 0) s_red[tid >> 5] = m;
    }
    __syncthreads();
    float emax = fmaxf(s_red[0], s_red[1]);
    float p = 0.f;
    if (tid < 64) {
        p = (tid < K) ? __expf(e - emax) : 0.f;
        float ssum = p;
        #pragma unroll
        for (int o = 16; o; o >>= 1) ssum += __shfl_xor_sync(0xffffffffu, ssum, o);
        if ((tid & 31) == 0) s_red[2 + (tid >> 5)] = ssum;
    }
    __syncthreads();
    float denom = s_red[2] + s_red[3];
    if (tid < K) s_att[tid] = p / denom;
    __syncthreads();

    if (tid < 64) {
        float acc = 0.f;
        #pragma unroll 4
        for (int r2 = 0; r2 < K; r2++)
            acc += s_att[r2] * g_Wh[s_nbr[r2]*FOUT + tid];
        g_Wh2[i*FOUT + tid] = acc;
    }
    if (tid < K) {
        float aj = s_att[tid]; int rank = 0;
        for (int m2 = 0; m2 < K; m2++) {
            float am = s_att[m2]; int jm = s_nbr[m2];
            rank += (am > aj) || (am == aj && jm < jj);
        }
        g_src[i*MAXD + (K - 1 - rank)] = jj;
    }
    if (tid == 0) atomicAdd(&g_binCount[K - 1], 1);
}

// descending-length ordering
__global__ void k_scan() {
    if (threadIdx.x == 0) {
        int run = 0;
        for (int b = MAXD - 1; b >= 0; b--) { int v = g_binCount[b]; g_binCur[b] = run; run += v; }
    }
}

__global__ void k_assign(const int* __restrict__ seqlen) {
    int i = blockIdx.x * 256 + threadIdx.x;
    if (i < NN) {
        int L = seqlen[i];
        int slot = atomicAdd(&g_binCur[L - 1], 1);
        g_perm[slot] = i;
    }
}

// ---------------- Gx[j] = Wh2[j] @ w_ih^T + b ----------------
__global__ void k_gx(const float* __restrict__ wih, const float* __restrict__ bih,
                     const float* __restrict__ bhh) {
    extern __shared__ float s[];
    float* wT = s;              // [64][256]
    float* xr = s + HD*NG;      // [16][64]
    int row0 = blockIdx.x * 16;
    for (int idx = threadIdx.x; idx < NG*HD; idx += 256) {
        int g = idx >> 6, k = idx & 63;
        wT[k*NG + g] = wih[idx];
    }
    for (int idx = threadIdx.x; idx < 16*HD; idx += 256)
        xr[idx] = g_Wh2[row0*HD + idx];
    __syncthreads();
    int g = threadIdx.x;
    float b = bih[g] + bhh[g];
    int pos = (g & 31) * 8 + (g >> 5);
    for (int r = 0; r < 16; r++) {
        float acc = b;
        const float* x = xr + r*HD;
        #pragma unroll 8
        for (int k = 0; k < HD; k++) acc += x[k] * wT[k*NG + g];
        g_Gx[(row0 + r)*NG + pos] = acc;
    }
}

// ---------------- masked LSTM: warp-pair k-split, 4 rows/pair, 4 pairs/block ----------------
__device__ __forceinline__ float sigf(float x)  { return __fdividef(1.f, 1.f + __expf(-x)); }
__device__ __forceinline__ float tanhe(float x) { float e = __expf(2.f*x); return 1.f - __fdividef(2.f, e + 1.f); }

// smem: swA/swB 64KB weights (gate-pair packed, 16B lane stride, conflict-free)
//       hbf: 4 pairs x 64 k x 4 rows u64 (8KB)   duplicated-h broadcast buffer
//       xch: 4 pairs x 2 warps x 4 x 32 ulonglong2 (16KB) partial-sum exchange
#define LSTM_SMEM (64*1024 + 8*1024 + 16*1024)

__global__ void __launch_bounds__(256)
k_lstm(const int* __restrict__ seqlen, const float* __restrict__ whh, float* __restrict__ out) {
    extern __shared__ char smem_raw[];
    ulonglong2* swA = reinterpret_cast<ulonglong2*>(smem_raw);
    ulonglong2* swB = swA + 64*32;
    u64*        hbf = reinterpret_cast<u64*>(swB + 64*32);
    ulonglong2* xch = reinterpret_cast<ulonglong2*>(hbf + 4*64*4);

    for (int idx = threadIdx.x; idx < 64*32; idx += 256) {
        int k = idx >> 5, ln = idx & 31;
        ulonglong2 A, B;
        A.x = pack2(whh[(ln      )*HD + k], whh[(ln+ 32)*HD + k]);   // i pair
        A.y = pack2(whh[(ln+  64)*HD + k], whh[(ln+ 96)*HD + k]);   // f pair
        B.x = pack2(whh[(ln+ 128)*HD + k], whh[(ln+160)*HD + k]);   // g pair
        B.y = pack2(whh[(ln+ 192)*HD + k], whh[(ln+224)*HD + k]);   // o pair
        swA[idx] = A; swB[idx] = B;
    }

    int warp = threadIdx.x >> 5, lane = threadIdx.x & 31;
    int pair = warp >> 1, sub = warp & 1;       // sub 0: k 0..31, epi rows 0,1 ; sub 1: k 32..63, epi rows 2,3
    u64*        hb  = hbf + pair * 256;                 // [k][r]
    ulonglong2* xme = xch + (pair*2 + sub)     * 128;   // my stores (partials for other's rows)
    ulonglong2* xot = xch + (pair*2 + (1-sub)) * 128;   // other's stores (partials for my rows)
    int er = 2*sub;          // my epilogue rows er, er+1
    int sr = 2*(1-sub);      // rows whose partials I ship

    int slot0 = (blockIdx.x * 4 + pair) * 4;
    int rows[4], L[4]; int maxL = 0;
    #pragma unroll
    for (int r = 0; r < 4; r++) {
        rows[r] = g_perm[slot0 + r];
        L[r]    = seqlen[rows[r]];
        maxL    = L[r] > maxL ? L[r] : maxL;
    }
    float h0[2] = {0,0}, h1[2] = {0,0}, c0[2] = {0,0}, c1[2] = {0,0};

    // init my rows' h buffer to zero
    hb[lane*4 + er]        = 0ull;  hb[lane*4 + er + 1]        = 0ull;
    hb[(lane+32)*4 + er]   = 0ull;  hb[(lane+32)*4 + er + 1]   = 0ull;
    __syncthreads();    // weights + hb ready

    int kbase = sub * 32;
    int barid = 1 + pair;

    for (int t = 0; t < maxL; t++) {
        u64 acc[4][4];
        #pragma unroll
        for (int p = 0; p < 4; p++) { acc[sr][p] = 0ull; acc[sr+1][p] = 0ull; }
        #pragma unroll
        for (int j = 0; j < 2; j++) {
            if (t < L[er+j]) {                       // warp-uniform
                int src = g_src[rows[er+j]*MAXD + t];
                const ulonglong2* gp = reinterpret_cast<const ulonglong2*>(g_Gx + (size_t)src*NG + lane*8);
                ulonglong2 A = gp[0], B = gp[1];
                acc[er+j][0]=A.x; acc[er+j][1]=A.y; acc[er+j][2]=B.x; acc[er+j][3]=B.y;
            } else {
                #pragma unroll
                for (int p = 0; p < 4; p++) acc[er+j][p] = 0ull;
            }
        }

        #pragma unroll 4
        for (int kk = 0; kk < 32; kk++) {
            int k = kbase + kk;
            ulonglong2 hba = *reinterpret_cast<ulonglong2*>(hb + k*4);       // rows 0,1 (broadcast)
            ulonglong2 hbb = *reinterpret_cast<ulonglong2*>(hb + k*4 + 2);   // rows 2,3
            u64 b[4] = {hba.x, hba.y, hbb.x, hbb.y};
            ulonglong2 WA = swA[k*32 + lane];
            ulonglong2 WB = swB[k*32 + lane];
            u64 w[4] = {WA.x, WA.y, WB.x, WB.y};
            #pragma unroll
            for (int r = 0; r < 4; r++) {
                #pragma unroll
                for (int p = 0; p < 4; p++) fma2(acc[r][p], b[r], w[p]);
            }
        }

        // ship partials for the other warp's rows (conflict-free: 16B lane stride)
        xme[0*32 + lane] = make_ulonglong2(acc[sr][0],   acc[sr][1]);
        xme[1*32 + lane] = make_ulonglong2(acc[sr][2],   acc[sr][3]);
        xme[2*32 + lane] = make_ulonglong2(acc[sr+1][0], acc[sr+1][1]);
        xme[3*32 + lane] = make_ulonglong2(acc[sr+1][2], acc[sr+1][3]);
        barpair(barid);
        {
            ulonglong2 P0 = xot[0*32 + lane], P1 = xot[1*32 + lane];
            ulonglong2 P2 = xot[2*32 + lane], P3 = xot[3*32 + lane];
            acc[er][0]   = add2(acc[er][0],   P0.x);  acc[er][1]   = add2(acc[er][1],   P0.y);
            acc[er][2]   = add2(acc[er][2],   P1.x);  acc[er][3]   = add2(acc[er][3],   P1.y);
            acc[er+1][0] = add2(acc[er+1][0], P2.x);  acc[er+1][1] = add2(acc[er+1][1], P2.y);
            acc[er+1][2] = add2(acc[er+1][2], P3.x);  acc[er+1][3] = add2(acc[er+1][3], P3.y);
        }

        #pragma unroll
        for (int j = 0; j < 2; j++) {
            if (t < L[er+j]) {
                float2 gi = unpack2(acc[er+j][0]);
                float2 gf = unpack2(acc[er+j][1]);
                float2 gg = unpack2(acc[er+j][2]);
                float2 go = unpack2(acc[er+j][3]);
                float i0 = sigf(gi.x),  i1 = sigf(gi.y);
                float f0 = sigf(gf.x),  f1 = sigf(gf.y);
                float g0 = tanhe(gg.x), g1 = tanhe(gg.y);
                float o0 = sigf(go.x),  o1 = sigf(go.y);
                c0[j] = f0*c0[j] + i0*g0;
                c1[j] = f1*c1[j] + i1*g1;
                h0[j] = o0 * tanhe(c0[j]);
                h1[j] = o1 * tanhe(c1[j]);
            }
        }
        // publish my rows' h for next step
        hb[lane*4 + er]          = pack2(h0[0], h0[0]);
        hb[lane*4 + er + 1]      = pack2(h0[1], h0[1]);
        hb[(lane+32)*4 + er]     = pack2(h1[0], h1[0]);
        hb[(lane+32)*4 + er + 1] = pack2(h1[1], h1[1]);
        barpair(barid);   // hb ready AND xot consumed -> safe to overwrite next iter
    }

    #pragma unroll
    for (int j = 0; j < 2; j++) {
        out[rows[er+j]*HD + lane]      = h0[j];
        out[rows[er+j]*HD + lane + 32] = h1[j];
    }
}

// ---------------- launch ----------------
extern "C" void kernel_launch(void* const* d_in, const int* in_sizes, int n_in,
                              void* d_out, int out_size) {
    const float* h      = (const float*)d_in[0];
    const float* adj    = (const float*)d_in[1];
    const int*   seqlen = (const int*)  d_in[2];
    const float* W      = (const float*)d_in[3];
    const float* a      = (const float*)d_in[4];
    const float* wih    = (const float*)d_in[5];
    const float* whh    = (const float*)d_in[6];
    const float* bih    = (const float*)d_in[7];
    const float* bhh    = (const float*)d_in[8];
    float* out = (float*)d_out;

    cudaFuncSetAttribute(k_gx,   cudaFuncAttributeMaxDynamicSharedMemorySize, (HD*NG + 16*HD)*4);
    cudaFuncSetAttribute(k_lstm, cudaFuncAttributeMaxDynamicSharedMemorySize, LSTM_SMEM);

    k_init  <<<1, 64>>>();
    k_wh    <<<NN/16, 256>>>(h, W);
    k_s12   <<<NN/8, 256>>>(a);
    k_att   <<<NN, 256>>>(adj, seqlen);
    k_scan  <<<1, 32>>>();
    k_assign<<<NN/256, 256>>>(seqlen);
    k_gx    <<<NN/16, 256, (HD*NG + 16*HD)*4>>>(wih, bih, bhh);
    // warp-pair k-split: 16 rows/block, 256 threads, 88KB smem -> 2 blocks/SM, single wave
    k_lstm  <<<NN/16, 256, LSTM_SMEM>>>(seqlen, whh, out);
}

// round 10
// speedup vs baseline: 1.3530x; 1.3530x over previous
#include <cuda_runtime.h>
#include <cstdint>

#define NN   4096
#define FIN  256
#define FOUT 64
#define HD   64
#define MAXD 64
#define NG   256   // 4*HD

typedef unsigned long long u64;

// ---------------- scratch ----------------
__device__ float g_Wh [NN*FOUT];
__device__ float g_Wh2[NN*FOUT];
__device__ float g_s1 [NN];
__device__ float g_s2 [NN];
__device__ int   g_src[NN*MAXD];
__device__ float g_Gx [NN*NG];       // [j][(g&31)*8 + (g>>5)]  (lane*8 + q)
__device__ int   g_binCount[MAXD];
__device__ int   g_binCur  [MAXD];
__device__ int   g_perm[NN];         // rows sorted by seq_length DESCENDING

__global__ void k_init() { if (threadIdx.x < MAXD) g_binCount[threadIdx.x] = 0; }

// ---------------- f32x2 helpers ----------------
__device__ __forceinline__ void fma2(u64& d, u64 a, u64 b) {
    asm("fma.rn.f32x2 %0, %1, %2, %0;" : "+l"(d) : "l"(a), "l"(b));
}
__device__ __forceinline__ u64 pack2(float x, float y) {
    u64 r;
    asm("mov.b64 %0, {%1, %2};" : "=l"(r) : "r"(__float_as_uint(x)), "r"(__float_as_uint(y)));
    return r;
}
__device__ __forceinline__ float2 unpack2(u64 v) {
    unsigned lo, hi;
    asm("mov.b64 {%0, %1}, %2;" : "=r"(lo), "=r"(hi) : "l"(v));
    float2 f; f.x = __uint_as_float(lo); f.y = __uint_as_float(hi);
    return f;
}

// ---------------- Wh = h @ W ----------------
__global__ void k_wh(const float* __restrict__ h, const float* __restrict__ W) {
    __shared__ float sh[16*FIN];
    int row0 = blockIdx.x * 16;
    for (int idx = threadIdx.x; idx < 16*FIN; idx += 256)
        sh[idx] = h[row0*FIN + idx];
    __syncthreads();
    int f   = threadIdx.x & 63;
    int grp = threadIdx.x >> 6;
    const float* hr = sh + grp*4*FIN;
    float a0=0.f, a1=0.f, a2=0.f, a3=0.f;
    for (int k = 0; k < FIN; k++) {
        float w = W[k*FOUT + f];
        a0 += hr[k]*w; a1 += hr[FIN+k]*w; a2 += hr[2*FIN+k]*w; a3 += hr[3*FIN+k]*w;
    }
    int r0 = row0 + grp*4;
    g_Wh[(r0+0)*FOUT+f]=a0; g_Wh[(r0+1)*FOUT+f]=a1;
    g_Wh[(r0+2)*FOUT+f]=a2; g_Wh[(r0+3)*FOUT+f]=a3;
}

// ---------------- s1 = Wh@a1, s2 = Wh@a2 ----------------
__global__ void k_s12(const float* __restrict__ a) {
    int w    = (blockIdx.x*blockDim.x + threadIdx.x) >> 5;
    int lane = threadIdx.x & 31;
    float w0 = g_Wh[w*FOUT + lane], w1 = g_Wh[w*FOUT + lane + 32];
    float v1 = w0*a[lane]      + w1*a[lane+32];
    float v2 = w0*a[FOUT+lane] + w1*a[FOUT+lane+32];
    #pragma unroll
    for (int o = 16; o; o >>= 1) {
        v1 += __shfl_down_sync(0xffffffffu, v1, o);
        v2 += __shfl_down_sync(0xffffffffu, v2, o);
    }
    if (lane == 0) { g_s1[w] = v1; g_s2[w] = v2; }
}

// ---------------- attention ----------------
__global__ void k_att(const float* __restrict__ adj, const int* __restrict__ seqlen) {
    __shared__ int   s_wsum[8];
    __shared__ int   s_woff[8];
    __shared__ int   s_total;
    __shared__ int   s_nbr[MAXD];
    __shared__ float s_att[MAXD];
    __shared__ float s_red[4];
    int i    = blockIdx.x;
    int tid  = threadIdx.x;
    int lane = tid & 31;
    int wid  = tid >> 5;
    const float4* arow4 = reinterpret_cast<const float4*>(adj + (size_t)i * NN);

    float4 v0 = arow4[tid];
    float4 v1 = arow4[tid + 256];
    float4 v2 = arow4[tid + 512];
    float4 v3 = arow4[tid + 768];
    int loc[16]; int c = 0;
    {
        int j0 = 4*tid;
        if (v0.x>0.f) loc[c++]=j0;   if (v0.y>0.f) loc[c++]=j0+1;
        if (v0.z>0.f) loc[c++]=j0+2; if (v0.w>0.f) loc[c++]=j0+3;
        int j1 = 4*(tid+256);
        if (v1.x>0.f) loc[c++]=j1;   if (v1.y>0.f) loc[c++]=j1+1;
        if (v1.z>0.f) loc[c++]=j1+2; if (v1.w>0.f) loc[c++]=j1+3;
        int j2 = 4*(tid+512);
        if (v2.x>0.f) loc[c++]=j2;   if (v2.y>0.f) loc[c++]=j2+1;
        if (v2.z>0.f) loc[c++]=j2+2; if (v2.w>0.f) loc[c++]=j2+3;
        int j3 = 4*(tid+768);
        if (v3.x>0.f) loc[c++]=j3;   if (v3.y>0.f) loc[c++]=j3+1;
        if (v3.z>0.f) loc[c++]=j3+2; if (v3.w>0.f) loc[c++]=j3+3;
    }
    int inc = c;
    #pragma unroll
    for (int o = 1; o < 32; o <<= 1) {
        int n = __shfl_up_sync(0xffffffffu, inc, o);
        if (lane >= o) inc += n;
    }
    if (lane == 31) s_wsum[wid] = inc;
    __syncthreads();
    if (tid < 8) {
        int v = s_wsum[tid];
        #pragma unroll
        for (int o = 1; o < 8; o <<= 1) {
            int n = __shfl_up_sync(0xffu, v, o);
            if (tid >= o) v += n;
        }
        s_woff[tid] = v - s_wsum[tid];
        if (tid == 7) s_total = v;
    }
    __syncthreads();
    int base = s_woff[wid] + inc - c;
    for (int j = 0; j < c; j++) s_nbr[base + j] = loc[j];
    int K = s_total;
    __syncthreads();

    float e = 0.f; int jj = -1;
    if (tid < K) {
        jj = s_nbr[tid];
        float v = g_s1[i] + g_s2[jj];
        e = v > 0.f ? v : 0.2f * v;
    }
    if (tid < 64) {
        float m = (tid < K) ? e : -3.0e38f;
        #pragma unroll
        for (int o = 16; o; o >>= 1) m = fmaxf(m, __shfl_xor_sync(0xffffffffu, m, o));
        if ((tid & 31) == 0) s_red[tid >> 5] = m;
    }
    __syncthreads();
    float emax = fmaxf(s_red[0], s_red[1]);
    float p = 0.f;
    if (tid < 64) {
        p = (tid < K) ? __expf(e - emax) : 0.f;
        float ssum = p;
        #pragma unroll
        for (int o = 16; o; o >>= 1) ssum += __shfl_xor_sync(0xffffffffu, ssum, o);
        if ((tid & 31) == 0) s_red[2 + (tid >> 5)] = ssum;
    }
    __syncthreads();
    float denom = s_red[2] + s_red[3];
    if (tid < K) s_att[tid] = p / denom;
    __syncthreads();

    if (tid < 64) {
        float acc = 0.f;
        #pragma unroll 4
        for (int r2 = 0; r2 < K; r2++)
            acc += s_att[r2] * g_Wh[s_nbr[r2]*FOUT + tid];
        g_Wh2[i*FOUT + tid] = acc;
    }
    if (tid < K) {
        float aj = s_att[tid]; int rank = 0;
        for (int m2 = 0; m2 < K; m2++) {
            float am = s_att[m2]; int jm = s_nbr[m2];
            rank += (am > aj) || (am == aj && jm < jj);
        }
        g_src[i*MAXD + (K - 1 - rank)] = jj;
    }
    if (tid == 0) atomicAdd(&g_binCount[K - 1], 1);
}

// descending-length ordering
__global__ void k_scan() {
    if (threadIdx.x == 0) {
        int run = 0;
        for (int b = MAXD - 1; b >= 0; b--) { int v = g_binCount[b]; g_binCur[b] = run; run += v; }
    }
}

__global__ void k_assign(const int* __restrict__ seqlen) {
    int i = blockIdx.x * 256 + threadIdx.x;
    if (i < NN) {
        int L = seqlen[i];
        int slot = atomicAdd(&g_binCur[L - 1], 1);
        g_perm[slot] = i;
    }
}

// ---------------- Gx[j] = Wh2[j] @ w_ih^T + b ----------------
__global__ void k_gx(const float* __restrict__ wih, const float* __restrict__ bih,
                     const float* __restrict__ bhh) {
    extern __shared__ float s[];
    float* wT = s;              // [64][256]
    float* xr = s + HD*NG;      // [16][64]
    int row0 = blockIdx.x * 16;
    for (int idx = threadIdx.x; idx < NG*HD; idx += 256) {
        int g = idx >> 6, k = idx & 63;
        wT[k*NG + g] = wih[idx];
    }
    for (int idx = threadIdx.x; idx < 16*HD; idx += 256)
        xr[idx] = g_Wh2[row0*HD + idx];
    __syncthreads();
    int g = threadIdx.x;
    float b = bih[g] + bhh[g];
    int pos = (g & 31) * 8 + (g >> 5);
    for (int r = 0; r < 16; r++) {
        float acc = b;
        const float* x = xr + r*HD;
        #pragma unroll 8
        for (int k = 0; k < HD; k++) acc += x[k] * wT[k*NG + g];
        g_Gx[(row0 + r)*NG + pos] = acc;
    }
}

// ---------------- masked LSTM: 1 warp/SMSP, balanced persistent slots ----------------
__device__ __forceinline__ float sigf(float x)  { return __fdividef(1.f, 1.f + __expf(-x)); }
__device__ __forceinline__ float tanhe(float x) { float e = __expf(2.f*x); return 1.f - __fdividef(2.f, e + 1.f); }

// smem: swA/swB 64KB weights (gate-pair packed, 16B lane stride, conflict-free)
//       hbf: 4 warps x 64 k x 4 rows u64 (8KB) duplicated-h broadcast buffer
#define LSTM_SMEM (64*1024 + 8*1024)
#define NGRPS   (NN/4)        // 1024 row-groups (sorted desc)
#define NSLOTS  592           // 148 blocks x 4 warps
#define NSINGLE 160           // longest groups get dedicated slots
// remaining 864 groups paired {NSINGLE+j, NGRPS-1-j}, j=0..431 (sum-L ~const)

__global__ void __launch_bounds__(128)
k_lstm(const int* __restrict__ seqlen, const float* __restrict__ whh, float* __restrict__ out) {
    extern __shared__ char smem_raw[];
    ulonglong2* swA = reinterpret_cast<ulonglong2*>(smem_raw);
    ulonglong2* swB = swA + 64*32;
    u64*        hbf = reinterpret_cast<u64*>(swB + 64*32);

    for (int idx = threadIdx.x; idx < 64*32; idx += 128) {
        int k = idx >> 5, ln = idx & 31;
        ulonglong2 A, B;
        A.x = pack2(whh[(ln      )*HD + k], whh[(ln+ 32)*HD + k]);   // i pair
        A.y = pack2(whh[(ln+  64)*HD + k], whh[(ln+ 96)*HD + k]);   // f pair
        B.x = pack2(whh[(ln+ 128)*HD + k], whh[(ln+160)*HD + k]);   // g pair
        B.y = pack2(whh[(ln+ 192)*HD + k], whh[(ln+224)*HD + k]);   // o pair
        swA[idx] = A; swB[idx] = B;
    }
    __syncthreads();

    int warp = threadIdx.x >> 5, lane = threadIdx.x & 31;
    u64* hb = hbf + warp * 256;          // [k][r]

    // balanced slot -> group list
    int slot = blockIdx.x * 4 + warp;
    int glist[2]; int ngrp;
    if (slot < NSINGLE) { glist[0] = slot; ngrp = 1; }
    else {
        int j = slot - NSINGLE;          // 0..431
        glist[0] = NSINGLE + j;
        glist[1] = NGRPS - 1 - j;
        ngrp = 2;
    }

    for (int gi = 0; gi < ngrp; gi++) {
        int slot0 = glist[gi] * 4;
        int rows[4], L[4]; int maxL = 0;
        #pragma unroll
        for (int r = 0; r < 4; r++) {
            rows[r] = g_perm[slot0 + r];
            L[r]    = seqlen[rows[r]];
            maxL    = L[r] > maxL ? L[r] : maxL;
        }
        float h0[4] = {0,0,0,0}, h1[4] = {0,0,0,0}, c0[4] = {0,0,0,0}, c1[4] = {0,0,0,0};

        for (int t = 0; t < maxL; t++) {
            // issue Gx loads first (L2-latency overlaps h staging)
            u64 acc2[4][4];
            #pragma unroll
            for (int r = 0; r < 4; r++) {
                if (t < L[r]) {                         // warp-uniform
                    int src = g_src[rows[r]*MAXD + t];
                    const ulonglong2* gp = reinterpret_cast<const ulonglong2*>(g_Gx + (size_t)src*NG + lane*8);
                    ulonglong2 A = gp[0], B = gp[1];
                    acc2[r][0]=A.x; acc2[r][1]=A.y; acc2[r][2]=B.x; acc2[r][3]=B.y;
                } else {
                    acc2[r][0]=0ull; acc2[r][1]=0ull; acc2[r][2]=0ull; acc2[r][3]=0ull;
                }
            }
            // stage duplicated h pairs: hb[k][r], k=lane -> h0, k=lane+32 -> h1
            #pragma unroll
            for (int r = 0; r < 4; r++) {
                hb[lane*4 + r]        = pack2(h0[r], h0[r]);
                hb[(lane+32)*4 + r]   = pack2(h1[r], h1[r]);
            }
            __syncwarp();

            #pragma unroll 4
            for (int k = 0; k < 32; k++) {
                // broadcast h pairs (warp-uniform addresses)
                ulonglong2 hb0a = *reinterpret_cast<ulonglong2*>(hb + k*4);
                ulonglong2 hb0b = *reinterpret_cast<ulonglong2*>(hb + k*4 + 2);
                ulonglong2 hb1a = *reinterpret_cast<ulonglong2*>(hb + (k+32)*4);
                ulonglong2 hb1b = *reinterpret_cast<ulonglong2*>(hb + (k+32)*4 + 2);
                u64 b0[4] = {hb0a.x, hb0a.y, hb0b.x, hb0b.y};
                u64 b1[4] = {hb1a.x, hb1a.y, hb1b.x, hb1b.y};
                // conflict-free weight loads (lane stride 16B)
                ulonglong2 WA0 = swA[k*32 + lane];
                ulonglong2 WB0 = swB[k*32 + lane];
                ulonglong2 WA1 = swA[(k+32)*32 + lane];
                ulonglong2 WB1 = swB[(k+32)*32 + lane];
                u64 w0[4] = {WA0.x, WA0.y, WB0.x, WB0.y};
                u64 w1[4] = {WA1.x, WA1.y, WB1.x, WB1.y};
                #pragma unroll
                for (int r = 0; r < 4; r++) {
                    #pragma unroll
                    for (int p = 0; p < 4; p++) {
                        fma2(acc2[r][p], b0[r], w0[p]);
                        fma2(acc2[r][p], b1[r], w1[p]);
                    }
                }
            }
            __syncwarp();
            #pragma unroll
            for (int r = 0; r < 4; r++) {
                if (t < L[r]) {
                    float2 gi2 = unpack2(acc2[r][0]);
                    float2 gf  = unpack2(acc2[r][1]);
                    float2 gg  = unpack2(acc2[r][2]);
                    float2 go  = unpack2(acc2[r][3]);
                    float i0 = sigf(gi2.x), i1 = sigf(gi2.y);
                    float f0 = sigf(gf.x),  f1 = sigf(gf.y);
                    float g0 = tanhe(gg.x), g1 = tanhe(gg.y);
                    float o0 = sigf(go.x),  o1 = sigf(go.y);
                    c0[r] = f0*c0[r] + i0*g0;
                    c1[r] = f1*c1[r] + i1*g1;
                    h0[r] = o0 * tanhe(c0[r]);
                    h1[r] = o1 * tanhe(c1[r]);
                }
            }
        }
        #pragma unroll
        for (int r = 0; r < 4; r++) {
            out[rows[r]*HD + lane]      = h0[r];
            out[rows[r]*HD + lane + 32] = h1[r];
        }
    }
}

// ---------------- launch ----------------
extern "C" void kernel_launch(void* const* d_in, const int* in_sizes, int n_in,
                              void* d_out, int out_size) {
    const float* h      = (const float*)d_in[0];
    const float* adj    = (const float*)d_in[1];
    const int*   seqlen = (const int*)  d_in[2];
    const float* W      = (const float*)d_in[3];
    const float* a      = (const float*)d_in[4];
    const float* wih    = (const float*)d_in[5];
    const float* whh    = (const float*)d_in[6];
    const float* bih    = (const float*)d_in[7];
    const float* bhh    = (const float*)d_in[8];
    float* out = (float*)d_out;

    cudaFuncSetAttribute(k_gx,   cudaFuncAttributeMaxDynamicSharedMemorySize, (HD*NG + 16*HD)*4);
    cudaFuncSetAttribute(k_lstm, cudaFuncAttributeMaxDynamicSharedMemorySize, LSTM_SMEM);

    k_init  <<<1, 64>>>();
    k_wh    <<<NN/16, 256>>>(h, W);
    k_s12   <<<NN/8, 256>>>(a);
    k_att   <<<NN, 256>>>(adj, seqlen);
    k_scan  <<<1, 32>>>();
    k_assign<<<NN/256, 256>>>(seqlen);
    k_gx    <<<NN/16, 256, (HD*NG + 16*HD)*4>>>(wih, bih, bhh);
    // 148 blocks x 4 warps = 592 slots, 1 block/SM, 1 warp/SMSP, balanced group assignment
    k_lstm  <<<148, 128, LSTM_SMEM>>>(seqlen, whh, out);
}